// round 5
// baseline (speedup 1.0000x reference)
#include <cuda_runtime.h>
#include <cuda_fp16.h>
#include <cuda_fp8.h>
#include <cstdint>

#define N_NODES 100000
#define N_EDGES 1600000
#define FNODE   32
#define FGLOB   16
#define HDIM    64
#define OUTDIM  64

#define MSG_SCALE    64.0f
#define INV_MSG_SCALE (1.0f / 64.0f)

#define SCAN_BS 1024
#define N_SCAN_BLOCKS ((N_NODES + SCAN_BS - 1) / SCAN_BS)   // 98

// ---------------- scratch (device globals: no allocations allowed) ----------
__device__ int   g_cnt[N_NODES];
__device__ int   g_cursor[N_NODES];
__device__ int   g_rowoff[N_NODES];          // block-local exclusive scan
__device__ int   g_bsum[N_SCAN_BLOCKS];      // exclusive block offsets
__device__ __align__(16) int g_csr[N_EDGES];
__device__ float g_dis[N_NODES];
__device__ __align__(16) __half g_hf[(size_t)N_NODES * HDIM];            // node features fp16
__device__ __align__(16) unsigned short g_hw8[(size_t)N_NODES * 32];     // fp8x2 messages, 64B/row
__device__ float g_pool[HDIM];

// ---------------- init ---------------------------------------------------------
__global__ void k_init() {
    int i = blockIdx.x * blockDim.x + threadIdx.x;
    if (i < N_NODES) g_cnt[i] = 0;
    if (i < HDIM) g_pool[i] = 0.f;
}

// ---------------- degree count over dst ----------------------------------------
__global__ void k_count(const int* __restrict__ dst) {
    int e = blockIdx.x * blockDim.x + threadIdx.x;
    if (e < N_EDGES) atomicAdd(&g_cnt[dst[e]], 1);
}

// ---------------- scan stage 1 (shuffle-based) + dis + cursor zero --------------
__global__ void k_scan1() {
    __shared__ int wsum[32];
    int tid = threadIdx.x;
    int i = blockIdx.x * SCAN_BS + tid;
    int v = (i < N_NODES) ? g_cnt[i] : 0;
    if (i < N_NODES) {
        g_dis[i] = rsqrtf((float)(v + 1));
        g_cursor[i] = 0;
    }

    int lane = tid & 31, w = tid >> 5;
    int s = v;
    #pragma unroll
    for (int o = 1; o < 32; o <<= 1) {
        int t = __shfl_up_sync(0xffffffffu, s, o);
        if (lane >= o) s += t;
    }
    if (lane == 31) wsum[w] = s;
    __syncthreads();
    if (w == 0) {
        int ws = wsum[lane];
        int t = ws;
        #pragma unroll
        for (int o = 1; o < 32; o <<= 1) {
            int u = __shfl_up_sync(0xffffffffu, t, o);
            if (lane >= o) t += u;
        }
        wsum[lane] = t - ws;
        if (lane == 31) g_bsum[blockIdx.x] = t;
    }
    __syncthreads();
    if (i < N_NODES) g_rowoff[i] = wsum[w] + s - v;
}

// ---------------- scan stage 2 --------------------------------------------------
__global__ void k_scan2() {
    __shared__ int wsum[4];
    int tid = threadIdx.x;                 // 128 threads
    int v = (tid < N_SCAN_BLOCKS) ? g_bsum[tid] : 0;
    int lane = tid & 31, w = tid >> 5;
    int s = v;
    #pragma unroll
    for (int o = 1; o < 32; o <<= 1) {
        int t = __shfl_up_sync(0xffffffffu, s, o);
        if (lane >= o) s += t;
    }
    if (lane == 31) wsum[w] = s;
    __syncthreads();
    int woff = 0;
    #pragma unroll
    for (int k = 0; k < 4; k++) if (k < w) woff += wsum[k];
    if (tid < N_SCAN_BLOCKS) g_bsum[tid] = woff + s - v;
}

// ---------------- CSR fill ------------------------------------------------------
__global__ void k_fill(const int* __restrict__ src, const int* __restrict__ dst) {
    int e = blockIdx.x * blockDim.x + threadIdx.x;
    if (e < N_EDGES) {
        int d = dst[e];
        int base = g_rowoff[d] + g_bsum[d >> 10];
        int pos = base + atomicAdd(&g_cursor[d], 1);
        g_csr[pos] = src[e];
    }
}

// ---------------- embedding GEMM: hf[N,64] = fp16(x[N,32] @ W + b) --------------
__global__ void k_embed(const float* __restrict__ in, const float* __restrict__ w,
                        const float* __restrict__ bias, __half* __restrict__ out) {
    __shared__ float4 Ws4[FNODE * 16];
    __shared__ float Bs[HDIM];
    int tid = threadIdx.x;
    for (int j = tid; j < FNODE * 16; j += blockDim.x)
        Ws4[j] = reinterpret_cast<const float4*>(w)[j];
    if (tid < HDIM) Bs[tid] = bias[tid];
    __syncthreads();

    int colBase = (tid & 1) * 32;
    int cb4 = colBase >> 2;
    int pair = tid >> 1;
    int r0 = blockIdx.x * 256 + pair * 2;
    if (r0 >= N_NODES) return;
    bool v1 = (r0 + 1 < N_NODES);

    float acc0[32], acc1[32];
    #pragma unroll
    for (int c = 0; c < 32; c++) { acc0[c] = 0.f; acc1[c] = 0.f; }

    const float4* xr0 = reinterpret_cast<const float4*>(in + (size_t)r0 * FNODE);
    const float4* xr1 = reinterpret_cast<const float4*>(in + (size_t)(v1 ? r0 + 1 : r0) * FNODE);

    #pragma unroll
    for (int k4 = 0; k4 < FNODE / 4; ++k4) {
        float4 a = __ldg(&xr0[k4]);
        float4 b = __ldg(&xr1[k4]);
        const float av[4] = {a.x, a.y, a.z, a.w};
        const float bv[4] = {b.x, b.y, b.z, b.w};
        #pragma unroll
        for (int kk = 0; kk < 4; ++kk) {
            const float4* wrow = &Ws4[(k4 * 4 + kk) * 16 + cb4];
            float xa = av[kk], xb = bv[kk];
            #pragma unroll
            for (int c4 = 0; c4 < 8; c4++) {
                float4 wv = wrow[c4];
                acc0[c4*4+0] += xa * wv.x; acc1[c4*4+0] += xb * wv.x;
                acc0[c4*4+1] += xa * wv.y; acc1[c4*4+1] += xb * wv.y;
                acc0[c4*4+2] += xa * wv.z; acc1[c4*4+2] += xb * wv.z;
                acc0[c4*4+3] += xa * wv.w; acc1[c4*4+3] += xb * wv.w;
            }
        }
    }

    __half2 hb0[16], hb1[16];
    #pragma unroll
    for (int c2 = 0; c2 < 16; c2++) {
        hb0[c2] = __floats2half2_rn(acc0[2*c2] + Bs[colBase + 2*c2],
                                    acc0[2*c2+1] + Bs[colBase + 2*c2 + 1]);
        hb1[c2] = __floats2half2_rn(acc1[2*c2] + Bs[colBase + 2*c2],
                                    acc1[2*c2+1] + Bs[colBase + 2*c2 + 1]);
    }
    uint4* o0 = reinterpret_cast<uint4*>(out + (size_t)r0 * HDIM + colBase);
    const uint4* p0 = reinterpret_cast<const uint4*>(hb0);
    #pragma unroll
    for (int q = 0; q < 4; q++) o0[q] = p0[q];
    if (v1) {
        uint4* o1 = reinterpret_cast<uint4*>(out + (size_t)(r0 + 1) * HDIM + colBase);
        const uint4* p1 = reinterpret_cast<const uint4*>(hb1);
        #pragma unroll
        for (int q = 0; q < 4; q++) o1[q] = p1[q];
    }
}

// ---------------- HMMA conv transform: hw8 = fp8(64 * dis .* (hf @ W)) ----------
// Block: 256 threads = 8 warps, 128 rows. Warp computes 16x64 via m16n8k16 mma.
#define APITCH 72   // halves; 144B rows: 16B-aligned, conflict-free ldmatrix
__global__ void k_hmma(const __half* __restrict__ hin, const float* __restrict__ w,
                       unsigned short* __restrict__ out8) {
    __shared__ __half Wsm[HDIM * APITCH];
    __shared__ __half Asm[128 * APITCH];
    int tid = threadIdx.x;
    int lane = tid & 31, wid = tid >> 5;
    int rowBase = blockIdx.x * 128;

    // stage W (fp32 -> fp16)
    for (int i = tid; i < HDIM * HDIM; i += 256) {
        int r = i >> 6, c = i & 63;
        Wsm[r * APITCH + c] = __float2half(w[i]);
    }
    // stage A rows (uint2 = 4 halves, 8B aligned)
    for (int i = tid; i < 128 * 16; i += 256) {
        int r = i >> 4, c4 = i & 15;
        int gr = rowBase + r;
        uint2 v = make_uint2(0u, 0u);
        if (gr < N_NODES)
            v = *reinterpret_cast<const uint2*>(hin + (size_t)gr * HDIM + c4 * 4);
        *reinterpret_cast<uint2*>(&Asm[r * APITCH + c4 * 4]) = v;
    }
    __syncthreads();

    float acc[8][4];
    #pragma unroll
    for (int j = 0; j < 8; j++)
        #pragma unroll
        for (int q = 0; q < 4; q++) acc[j][q] = 0.f;

    uint32_t aAddr = (uint32_t)__cvta_generic_to_shared(
        &Asm[(wid * 16 + (lane & 15)) * APITCH + (lane >> 4) * 8]);
    uint32_t bAddr = (uint32_t)__cvta_generic_to_shared(
        &Wsm[(lane & 15) * APITCH]);

    #pragma unroll
    for (int k = 0; k < 4; k++) {
        uint32_t a0, a1, a2, a3;
        asm volatile("ldmatrix.sync.aligned.m8n8.x4.shared.b16 {%0,%1,%2,%3}, [%4];\n"
                     : "=r"(a0), "=r"(a1), "=r"(a2), "=r"(a3)
                     : "r"(aAddr + k * 16 * 2));
        #pragma unroll
        for (int j = 0; j < 8; j++) {
            uint32_t b0, b1;
            asm volatile("ldmatrix.sync.aligned.m8n8.x2.trans.shared.b16 {%0,%1}, [%2];\n"
                         : "=r"(b0), "=r"(b1)
                         : "r"(bAddr + (k * 16 * APITCH + j * 8) * 2));
            asm volatile("mma.sync.aligned.m16n8k16.row.col.f32.f16.f16.f32 "
                         "{%0,%1,%2,%3}, {%4,%5,%6,%7}, {%8,%9}, {%0,%1,%2,%3};\n"
                         : "+f"(acc[j][0]), "+f"(acc[j][1]), "+f"(acc[j][2]), "+f"(acc[j][3])
                         : "r"(a0), "r"(a1), "r"(a2), "r"(a3), "r"(b0), "r"(b1));
        }
    }

    // epilogue: scale rows by 64*dis, convert fp8x2, store (row = 32 ushorts)
    int g = lane >> 2;
    int c2i = lane & 3;                    // fp8x2 index within 4-col group
    int r0 = rowBase + wid * 16 + g;
    int r1 = r0 + 8;
    float d0 = (r0 < N_NODES) ? g_dis[r0] * MSG_SCALE : 0.f;
    float d1 = (r1 < N_NODES) ? g_dis[r1] * MSG_SCALE : 0.f;
    if (r0 < N_NODES) {
        unsigned short* o = out8 + (size_t)r0 * 32 + c2i;
        #pragma unroll
        for (int j = 0; j < 8; j++)
            o[j * 4] = __nv_cvt_float2_to_fp8x2(
                make_float2(acc[j][0] * d0, acc[j][1] * d0), __NV_SATFINITE, __NV_E4M3);
    }
    if (r1 < N_NODES) {
        unsigned short* o = out8 + (size_t)r1 * 32 + c2i;
        #pragma unroll
        for (int j = 0; j < 8; j++)
            o[j * 4] = __nv_cvt_float2_to_fp8x2(
                make_float2(acc[j][2] * d1, acc[j][3] * d1), __NV_SATFINITE, __NV_E4M3);
    }
}

// ---------------- fp8x2 -> half2 helper -----------------------------------------
__device__ __forceinline__ __half2 fp8x2_to_h2(unsigned short u) {
    __half2_raw hr = __nv_cvt_fp8x2_to_halfraw2(u, __NV_E4M3);
    return *reinterpret_cast<__half2*>(&hr);
}

// ---------------- aggregation: one warp per node, fp8 gather-sum ----------------
// hw8 rows (64B) pre-scaled by 64*dis[src]. hf[i] = fp16(relu(dis[i]/64*sum + b))
__global__ void k_agg(const unsigned short* __restrict__ hw8,
                      const float* __restrict__ bias, __half2* __restrict__ outh) {
    int gw = (blockIdx.x * blockDim.x + threadIdx.x) >> 5;
    int lane = threadIdx.x & 31;
    if (gw >= N_NODES) return;

    float2 b2 = __ldg(reinterpret_cast<const float2*>(bias) + lane);

    // self loop term (hw8 already includes 64*dis[i])
    float2 sf = __half22float2(fp8x2_to_h2(__ldg(&hw8[(size_t)gw * 32 + lane])));
    float2 acc = sf;

    int beg = g_rowoff[gw] + g_bsum[gw >> 10];
    int end = beg + g_cnt[gw];
    int j = beg;

    // align j to 4-edge boundary of g_csr (16B aligned base)
    while (j < end && (j & 3)) {
        float2 v = __half22float2(fp8x2_to_h2(__ldg(&hw8[(size_t)__ldg(&g_csr[j]) * 32 + lane])));
        acc.x += v.x; acc.y += v.y;
        ++j;
    }

    const int4* csr4 = reinterpret_cast<const int4*>(g_csr);
    // 8-edge blocks: 2 broadcast int4 loads + half2 tree, float master accumulate
    for (; j + 7 < end; j += 8) {
        int4 iA = __ldg(&csr4[j >> 2]);
        int4 iB = __ldg(&csr4[(j >> 2) + 1]);
        __half2 v0 = fp8x2_to_h2(__ldg(&hw8[(size_t)iA.x * 32 + lane]));
        __half2 v1 = fp8x2_to_h2(__ldg(&hw8[(size_t)iA.y * 32 + lane]));
        __half2 v2 = fp8x2_to_h2(__ldg(&hw8[(size_t)iA.z * 32 + lane]));
        __half2 v3 = fp8x2_to_h2(__ldg(&hw8[(size_t)iA.w * 32 + lane]));
        __half2 v4 = fp8x2_to_h2(__ldg(&hw8[(size_t)iB.x * 32 + lane]));
        __half2 v5 = fp8x2_to_h2(__ldg(&hw8[(size_t)iB.y * 32 + lane]));
        __half2 v6 = fp8x2_to_h2(__ldg(&hw8[(size_t)iB.z * 32 + lane]));
        __half2 v7 = fp8x2_to_h2(__ldg(&hw8[(size_t)iB.w * 32 + lane]));
        __half2 t01 = __hadd2(v0, v1), t23 = __hadd2(v2, v3);
        __half2 t45 = __hadd2(v4, v5), t67 = __hadd2(v6, v7);
        __half2 t = __hadd2(__hadd2(t01, t23), __hadd2(t45, t67));
        float2 f = __half22float2(t);
        acc.x += f.x; acc.y += f.y;
    }
    // 4-edge block
    if (j + 3 < end) {
        int4 iA = __ldg(&csr4[j >> 2]);
        __half2 v0 = fp8x2_to_h2(__ldg(&hw8[(size_t)iA.x * 32 + lane]));
        __half2 v1 = fp8x2_to_h2(__ldg(&hw8[(size_t)iA.y * 32 + lane]));
        __half2 v2 = fp8x2_to_h2(__ldg(&hw8[(size_t)iA.z * 32 + lane]));
        __half2 v3 = fp8x2_to_h2(__ldg(&hw8[(size_t)iA.w * 32 + lane]));
        __half2 t = __hadd2(__hadd2(v0, v1), __hadd2(v2, v3));
        float2 f = __half22float2(t);
        acc.x += f.x; acc.y += f.y;
        j += 4;
    }
    // tail
    for (; j < end; ++j) {
        float2 v = __half22float2(fp8x2_to_h2(__ldg(&hw8[(size_t)__ldg(&g_csr[j]) * 32 + lane])));
        acc.x += v.x; acc.y += v.y;
    }

    float di = g_dis[gw] * INV_MSG_SCALE;
    float ox = fmaxf(fmaf(di, acc.x, b2.x), 0.f);
    float oy = fmaxf(fmaf(di, acc.y, b2.y), 0.f);
    outh[(size_t)gw * 32 + lane] = __floats2half2_rn(ox, oy);
}

// ---------------- mean pool over nodes (fp16 input) ------------------------------
__global__ void k_pool(const __half2* __restrict__ h2) {
    __shared__ float2 sh[256];
    int c = threadIdx.x & 31;       // half2 column
    int seg = threadIdx.x >> 5;     // 0..7
    float2 acc = make_float2(0.f, 0.f);
    for (int r = blockIdx.x * 8 + seg; r < N_NODES; r += gridDim.x * 8) {
        float2 v = __half22float2(h2[(size_t)r * 32 + c]);
        acc.x += v.x; acc.y += v.y;
    }
    sh[threadIdx.x] = acc;
    __syncthreads();
    if (threadIdx.x < 32) {
        float2 s = sh[c];
        #pragma unroll
        for (int k = 1; k < 8; k++) {
            s.x += sh[k * 32 + c].x;
            s.y += sh[k * 32 + c].y;
        }
        atomicAdd(&g_pool[2 * c],     s.x);
        atomicAdd(&g_pool[2 * c + 1], s.y);
    }
}

// ---------------- head ------------------------------------------------------------
__global__ void k_head(const float* __restrict__ gf,
                       const float* __restrict__ w_glob, const float* __restrict__ b_glob,
                       const float* __restrict__ w_fc1, const float* __restrict__ b_fc1,
                       const float* __restrict__ w_fc2, const float* __restrict__ b_fc2,
                       float* __restrict__ out) {
    __shared__ float xc[2 * HDIM];
    __shared__ float t1[HDIM];
    int t = threadIdx.x;

    xc[t] = g_pool[t] * (1.0f / (float)N_NODES);

    float a = b_glob[t];
    #pragma unroll
    for (int k = 0; k < FGLOB; k++) a += gf[k] * w_glob[k * HDIM + t];
    xc[HDIM + t] = fmaxf(a, 0.f);
    __syncthreads();

    float u = b_fc1[t];
    #pragma unroll 8
    for (int k = 0; k < 2 * HDIM; k++) u += xc[k] * w_fc1[k * HDIM + t];
    t1[t] = fmaxf(u, 0.f);
    __syncthreads();

    float o = b_fc2[t];
    #pragma unroll 8
    for (int k = 0; k < HDIM; k++) o += t1[k] * w_fc2[k * OUTDIM + t];
    out[t] = o;
}

// ---------------- launch ------------------------------------------------------
extern "C" void kernel_launch(void* const* d_in, const int* in_sizes, int n_in,
                              void* d_out, int out_size) {
    const float* x      = (const float*)d_in[0];
    const int*   ei     = (const int*)  d_in[1];   // [2,E]: first E = src, next E = dst
    const float* gf     = (const float*)d_in[2];
    const float* w_node = (const float*)d_in[3];
    const float* b_node = (const float*)d_in[4];
    const float* w_glob = (const float*)d_in[5];
    const float* b_glob = (const float*)d_in[6];
    const float* w_c[3] = {(const float*)d_in[7], (const float*)d_in[9],  (const float*)d_in[11]};
    const float* b_c[3] = {(const float*)d_in[8], (const float*)d_in[10], (const float*)d_in[12]};
    const float* w_fc1  = (const float*)d_in[13];
    const float* b_fc1  = (const float*)d_in[14];
    const float* w_fc2  = (const float*)d_in[15];
    const float* b_fc2  = (const float*)d_in[16];
    float* out = (float*)d_out;

    __half *p_hf;
    unsigned short *p_hw8;
    cudaGetSymbolAddress((void**)&p_hf,  g_hf);
    cudaGetSymbolAddress((void**)&p_hw8, g_hw8);

    static cudaStream_t s_side = nullptr;
    static cudaEvent_t  s_evFork = nullptr, s_evDis = nullptr, s_evFill = nullptr;
    if (!s_side) {
        cudaStreamCreateWithFlags(&s_side, cudaStreamNonBlocking);
        cudaEventCreateWithFlags(&s_evFork, cudaEventDisableTiming);
        cudaEventCreateWithFlags(&s_evDis,  cudaEventDisableTiming);
        cudaEventCreateWithFlags(&s_evFill, cudaEventDisableTiming);
    }

    const int TB = 256;

    // fork: CSR build chain on side stream
    cudaEventRecord(s_evFork, 0);
    cudaStreamWaitEvent(s_side, s_evFork, 0);
    k_init <<<(N_NODES + TB - 1) / TB, TB, 0, s_side>>>();
    k_count<<<(N_EDGES + TB - 1) / TB, TB, 0, s_side>>>(ei + N_EDGES);
    k_scan1<<<N_SCAN_BLOCKS, SCAN_BS, 0, s_side>>>();           // writes dis + cursor
    cudaEventRecord(s_evDis, s_side);
    k_scan2<<<1, 128, 0, s_side>>>();
    k_fill <<<(N_EDGES + TB - 1) / TB, TB, 0, s_side>>>(ei, ei + N_EDGES);
    cudaEventRecord(s_evFill, s_side);

    // main: embedding (no deps)
    k_embed<<<(N_NODES + 255) / 256, 256>>>(x, w_node, b_node, p_hf);

    const int HG = (N_NODES + 127) / 128;   // 782 blocks

    // layer 1 transform needs only dis
    cudaStreamWaitEvent(0, s_evDis, 0);
    k_hmma<<<HG, 256>>>(p_hf, w_c[0], p_hw8);
    // agg needs CSR
    cudaStreamWaitEvent(0, s_evFill, 0);
    k_agg<<<(N_NODES * 32 + TB - 1) / TB, TB>>>(p_hw8, b_c[0], (__half2*)p_hf);

    for (int l = 1; l < 3; l++) {
        k_hmma<<<HG, 256>>>(p_hf, w_c[l], p_hw8);
        k_agg<<<(N_NODES * 32 + TB - 1) / TB, TB>>>(p_hw8, b_c[l], (__half2*)p_hf);
    }

    // pool + head
    k_pool<<<256, 256>>>((const __half2*)p_hf);
    k_head<<<1, 64>>>(gf, w_glob, b_glob, w_fc1, b_fc1, w_fc2, b_fc2, out);
}

// round 6
// speedup vs baseline: 1.0664x; 1.0664x over previous
#include <cuda_runtime.h>
#include <cuda_fp16.h>
#include <cuda_bf16.h>
#include <cstdint>

#define N_NODES 100000
#define N_EDGES 1600000
#define FNODE   32
#define FGLOB   16
#define HDIM    64
#define OUTDIM  64

#define SCAN_BS 1024
#define N_SCAN_BLOCKS ((N_NODES + SCAN_BS - 1) / SCAN_BS)   // 98

// ---------------- scratch (device globals: no allocations allowed) ----------
__device__ int   g_cnt[N_NODES];
__device__ int   g_cursor[N_NODES];
__device__ int   g_rowoff[N_NODES];          // block-local exclusive scan
__device__ int   g_bsum[N_SCAN_BLOCKS];      // exclusive block offsets
__device__ __align__(16) int g_csr[N_EDGES];
__device__ float g_dis[N_NODES];
__device__ __align__(16) __half g_hf[(size_t)N_NODES * HDIM];    // node features fp16
__device__ __align__(16) __half g_hwh[(size_t)N_NODES * HDIM];   // messages fp16, 128B/row
__device__ float g_pool[HDIM];

// ---------------- init ---------------------------------------------------------
__global__ void k_init() {
    int i = blockIdx.x * blockDim.x + threadIdx.x;
    if (i < N_NODES) g_cnt[i] = 0;
    if (i < HDIM) g_pool[i] = 0.f;
}

// ---------------- degree count over dst ----------------------------------------
__global__ void k_count(const int* __restrict__ dst) {
    int e = blockIdx.x * blockDim.x + threadIdx.x;
    if (e < N_EDGES) atomicAdd(&g_cnt[dst[e]], 1);
}

// ---------------- scan stage 1 (shuffle-based) + dis + cursor zero --------------
__global__ void k_scan1() {
    __shared__ int wsum[32];
    int tid = threadIdx.x;
    int i = blockIdx.x * SCAN_BS + tid;
    int v = (i < N_NODES) ? g_cnt[i] : 0;
    if (i < N_NODES) {
        g_dis[i] = rsqrtf((float)(v + 1));
        g_cursor[i] = 0;
    }

    int lane = tid & 31, w = tid >> 5;
    int s = v;
    #pragma unroll
    for (int o = 1; o < 32; o <<= 1) {
        int t = __shfl_up_sync(0xffffffffu, s, o);
        if (lane >= o) s += t;
    }
    if (lane == 31) wsum[w] = s;
    __syncthreads();
    if (w == 0) {
        int ws = wsum[lane];
        int t = ws;
        #pragma unroll
        for (int o = 1; o < 32; o <<= 1) {
            int u = __shfl_up_sync(0xffffffffu, t, o);
            if (lane >= o) t += u;
        }
        wsum[lane] = t - ws;
        if (lane == 31) g_bsum[blockIdx.x] = t;
    }
    __syncthreads();
    if (i < N_NODES) g_rowoff[i] = wsum[w] + s - v;
}

// ---------------- scan stage 2 --------------------------------------------------
__global__ void k_scan2() {
    __shared__ int wsum[4];
    int tid = threadIdx.x;                 // 128 threads
    int v = (tid < N_SCAN_BLOCKS) ? g_bsum[tid] : 0;
    int lane = tid & 31, w = tid >> 5;
    int s = v;
    #pragma unroll
    for (int o = 1; o < 32; o <<= 1) {
        int t = __shfl_up_sync(0xffffffffu, s, o);
        if (lane >= o) s += t;
    }
    if (lane == 31) wsum[w] = s;
    __syncthreads();
    int woff = 0;
    #pragma unroll
    for (int k = 0; k < 4; k++) if (k < w) woff += wsum[k];
    if (tid < N_SCAN_BLOCKS) g_bsum[tid] = woff + s - v;
}

// ---------------- CSR fill ------------------------------------------------------
__global__ void k_fill(const int* __restrict__ src, const int* __restrict__ dst) {
    int e = blockIdx.x * blockDim.x + threadIdx.x;
    if (e < N_EDGES) {
        int d = dst[e];
        int base = g_rowoff[d] + g_bsum[d >> 10];
        int pos = base + atomicAdd(&g_cursor[d], 1);
        g_csr[pos] = src[e];
    }
}

// ---------------- embedding GEMM: hf[N,64] = fp16(x[N,32] @ W + b) --------------
__global__ void k_embed(const float* __restrict__ in, const float* __restrict__ w,
                        const float* __restrict__ bias, __half* __restrict__ out) {
    __shared__ float4 Ws4[FNODE * 16];
    __shared__ float Bs[HDIM];
    int tid = threadIdx.x;
    for (int j = tid; j < FNODE * 16; j += blockDim.x)
        Ws4[j] = reinterpret_cast<const float4*>(w)[j];
    if (tid < HDIM) Bs[tid] = bias[tid];
    __syncthreads();

    int colBase = (tid & 1) * 32;
    int cb4 = colBase >> 2;
    int pair = tid >> 1;
    int r0 = blockIdx.x * 256 + pair * 2;
    if (r0 >= N_NODES) return;
    bool v1 = (r0 + 1 < N_NODES);

    float acc0[32], acc1[32];
    #pragma unroll
    for (int c = 0; c < 32; c++) { acc0[c] = 0.f; acc1[c] = 0.f; }

    const float4* xr0 = reinterpret_cast<const float4*>(in + (size_t)r0 * FNODE);
    const float4* xr1 = reinterpret_cast<const float4*>(in + (size_t)(v1 ? r0 + 1 : r0) * FNODE);

    #pragma unroll
    for (int k4 = 0; k4 < FNODE / 4; ++k4) {
        float4 a = __ldg(&xr0[k4]);
        float4 b = __ldg(&xr1[k4]);
        const float av[4] = {a.x, a.y, a.z, a.w};
        const float bv[4] = {b.x, b.y, b.z, b.w};
        #pragma unroll
        for (int kk = 0; kk < 4; ++kk) {
            const float4* wrow = &Ws4[(k4 * 4 + kk) * 16 + cb4];
            float xa = av[kk], xb = bv[kk];
            #pragma unroll
            for (int c4 = 0; c4 < 8; c4++) {
                float4 wv = wrow[c4];
                acc0[c4*4+0] += xa * wv.x; acc1[c4*4+0] += xb * wv.x;
                acc0[c4*4+1] += xa * wv.y; acc1[c4*4+1] += xb * wv.y;
                acc0[c4*4+2] += xa * wv.z; acc1[c4*4+2] += xb * wv.z;
                acc0[c4*4+3] += xa * wv.w; acc1[c4*4+3] += xb * wv.w;
            }
        }
    }

    __half2 hb0[16], hb1[16];
    #pragma unroll
    for (int c2 = 0; c2 < 16; c2++) {
        hb0[c2] = __floats2half2_rn(acc0[2*c2] + Bs[colBase + 2*c2],
                                    acc0[2*c2+1] + Bs[colBase + 2*c2 + 1]);
        hb1[c2] = __floats2half2_rn(acc1[2*c2] + Bs[colBase + 2*c2],
                                    acc1[2*c2+1] + Bs[colBase + 2*c2 + 1]);
    }
    uint4* o0 = reinterpret_cast<uint4*>(out + (size_t)r0 * HDIM + colBase);
    const uint4* p0 = reinterpret_cast<const uint4*>(hb0);
    #pragma unroll
    for (int q = 0; q < 4; q++) o0[q] = p0[q];
    if (v1) {
        uint4* o1 = reinterpret_cast<uint4*>(out + (size_t)(r0 + 1) * HDIM + colBase);
        const uint4* p1 = reinterpret_cast<const uint4*>(hb1);
        #pragma unroll
        for (int q = 0; q < 4; q++) o1[q] = p1[q];
    }
}

// ---------------- HMMA conv transform: hwh = fp16(dis .* (hf @ W)) --------------
// Block: 256 threads = 8 warps, 128 rows. Warp computes 16x64 via m16n8k16 mma.
#define APITCH 72   // halves; 144B rows: 16B-aligned, conflict-free ldmatrix
__global__ void k_hmma(const __half* __restrict__ hin, const float* __restrict__ w,
                       __half* __restrict__ outH) {
    __shared__ __half Wsm[HDIM * APITCH];
    __shared__ __half Asm[128 * APITCH];
    int tid = threadIdx.x;
    int lane = tid & 31, wid = tid >> 5;
    int rowBase = blockIdx.x * 128;

    // stage W (fp32 -> fp16)
    for (int i = tid; i < HDIM * HDIM; i += 256) {
        int r = i >> 6, c = i & 63;
        Wsm[r * APITCH + c] = __float2half(w[i]);
    }
    // stage A rows (uint2 = 4 halves, 8B aligned)
    for (int i = tid; i < 128 * 16; i += 256) {
        int r = i >> 4, c4 = i & 15;
        int gr = rowBase + r;
        uint2 v = make_uint2(0u, 0u);
        if (gr < N_NODES)
            v = *reinterpret_cast<const uint2*>(hin + (size_t)gr * HDIM + c4 * 4);
        *reinterpret_cast<uint2*>(&Asm[r * APITCH + c4 * 4]) = v;
    }
    __syncthreads();

    float acc[8][4];
    #pragma unroll
    for (int j = 0; j < 8; j++)
        #pragma unroll
        for (int q = 0; q < 4; q++) acc[j][q] = 0.f;

    uint32_t aAddr = (uint32_t)__cvta_generic_to_shared(
        &Asm[(wid * 16 + (lane & 15)) * APITCH + (lane >> 4) * 8]);
    uint32_t bAddr = (uint32_t)__cvta_generic_to_shared(
        &Wsm[(lane & 15) * APITCH]);

    #pragma unroll
    for (int k = 0; k < 4; k++) {
        uint32_t a0, a1, a2, a3;
        asm volatile("ldmatrix.sync.aligned.m8n8.x4.shared.b16 {%0,%1,%2,%3}, [%4];\n"
                     : "=r"(a0), "=r"(a1), "=r"(a2), "=r"(a3)
                     : "r"(aAddr + k * 16 * 2));
        #pragma unroll
        for (int j = 0; j < 8; j++) {
            uint32_t b0, b1;
            asm volatile("ldmatrix.sync.aligned.m8n8.x2.trans.shared.b16 {%0,%1}, [%2];\n"
                         : "=r"(b0), "=r"(b1)
                         : "r"(bAddr + (k * 16 * APITCH + j * 8) * 2));
            asm volatile("mma.sync.aligned.m16n8k16.row.col.f32.f16.f16.f32 "
                         "{%0,%1,%2,%3}, {%4,%5,%6,%7}, {%8,%9}, {%0,%1,%2,%3};\n"
                         : "+f"(acc[j][0]), "+f"(acc[j][1]), "+f"(acc[j][2]), "+f"(acc[j][3])
                         : "r"(a0), "r"(a1), "r"(a2), "r"(a3), "r"(b0), "r"(b1));
        }
    }

    // epilogue: scale rows by dis, convert fp16, store
    int g = lane >> 2, t2 = (lane & 3) * 2;
    int r0 = rowBase + wid * 16 + g;
    int r1 = r0 + 8;
    float d0 = (r0 < N_NODES) ? g_dis[r0] : 0.f;
    float d1 = (r1 < N_NODES) ? g_dis[r1] : 0.f;
    if (r0 < N_NODES) {
        __half* o = outH + (size_t)r0 * HDIM + t2;
        #pragma unroll
        for (int j = 0; j < 8; j++)
            *reinterpret_cast<__half2*>(o + j * 8) =
                __floats2half2_rn(acc[j][0] * d0, acc[j][1] * d0);
    }
    if (r1 < N_NODES) {
        __half* o = outH + (size_t)r1 * HDIM + t2;
        #pragma unroll
        for (int j = 0; j < 8; j++)
            *reinterpret_cast<__half2*>(o + j * 8) =
                __floats2half2_rn(acc[j][2] * d1, acc[j][3] * d1);
    }
}

// ---------------- aggregation: one warp per node, fp16 gather-sum ---------------
// hwh rows (128B) pre-scaled by dis[src]; edge indices read as int4 broadcasts.
__global__ void k_agg(const __half2* __restrict__ hw2, const float* __restrict__ bias,
                      __half2* __restrict__ outh) {
    int gw = (blockIdx.x * blockDim.x + threadIdx.x) >> 5;
    int lane = threadIdx.x & 31;
    if (gw >= N_NODES) return;

    float2 b2 = __ldg(reinterpret_cast<const float2*>(bias) + lane);

    // self loop term (hwh already includes dis[i])
    float2 accA = __half22float2(__ldg(&hw2[(size_t)gw * 32 + lane]));
    float2 accB = make_float2(0.f, 0.f);

    int beg = g_rowoff[gw] + g_bsum[gw >> 10];
    int end = beg + g_cnt[gw];
    int j = beg;

    // align to 4-edge boundary of g_csr (base is 16B aligned)
    while (j < end && (j & 3)) {
        float2 v = __half22float2(__ldg(&hw2[(size_t)__ldg(&g_csr[j]) * 32 + lane]));
        accA.x += v.x; accA.y += v.y;
        ++j;
    }

    const int4* csr4 = reinterpret_cast<const int4*>(g_csr);
    for (; j + 7 < end; j += 8) {
        int4 iA = __ldg(&csr4[j >> 2]);
        int4 iB = __ldg(&csr4[(j >> 2) + 1]);
        float2 v0 = __half22float2(__ldg(&hw2[(size_t)iA.x * 32 + lane]));
        float2 v1 = __half22float2(__ldg(&hw2[(size_t)iA.y * 32 + lane]));
        float2 v2 = __half22float2(__ldg(&hw2[(size_t)iA.z * 32 + lane]));
        float2 v3 = __half22float2(__ldg(&hw2[(size_t)iA.w * 32 + lane]));
        float2 v4 = __half22float2(__ldg(&hw2[(size_t)iB.x * 32 + lane]));
        float2 v5 = __half22float2(__ldg(&hw2[(size_t)iB.y * 32 + lane]));
        float2 v6 = __half22float2(__ldg(&hw2[(size_t)iB.z * 32 + lane]));
        float2 v7 = __half22float2(__ldg(&hw2[(size_t)iB.w * 32 + lane]));
        accA.x += v0.x + v1.x + v2.x + v3.x;
        accA.y += v0.y + v1.y + v2.y + v3.y;
        accB.x += v4.x + v5.x + v6.x + v7.x;
        accB.y += v4.y + v5.y + v6.y + v7.y;
    }
    if (j + 3 < end) {
        int4 iA = __ldg(&csr4[j >> 2]);
        float2 v0 = __half22float2(__ldg(&hw2[(size_t)iA.x * 32 + lane]));
        float2 v1 = __half22float2(__ldg(&hw2[(size_t)iA.y * 32 + lane]));
        float2 v2 = __half22float2(__ldg(&hw2[(size_t)iA.z * 32 + lane]));
        float2 v3 = __half22float2(__ldg(&hw2[(size_t)iA.w * 32 + lane]));
        accA.x += v0.x + v1.x + v2.x + v3.x;
        accA.y += v0.y + v1.y + v2.y + v3.y;
        j += 4;
    }
    for (; j < end; ++j) {
        float2 v = __half22float2(__ldg(&hw2[(size_t)__ldg(&g_csr[j]) * 32 + lane]));
        accA.x += v.x; accA.y += v.y;
    }

    float di = g_dis[gw];
    float ox = fmaxf(fmaf(di, accA.x + accB.x, b2.x), 0.f);
    float oy = fmaxf(fmaf(di, accA.y + accB.y, b2.y), 0.f);
    outh[(size_t)gw * 32 + lane] = __floats2half2_rn(ox, oy);
}

// ---------------- mean pool over nodes (fp16 input) ------------------------------
__global__ void k_pool(const __half2* __restrict__ h2) {
    __shared__ float2 sh[256];
    int c = threadIdx.x & 31;       // half2 column
    int seg = threadIdx.x >> 5;     // 0..7
    float2 acc = make_float2(0.f, 0.f);
    for (int r = blockIdx.x * 8 + seg; r < N_NODES; r += gridDim.x * 8) {
        float2 v = __half22float2(h2[(size_t)r * 32 + c]);
        acc.x += v.x; acc.y += v.y;
    }
    sh[threadIdx.x] = acc;
    __syncthreads();
    if (threadIdx.x < 32) {
        float2 s = sh[c];
        #pragma unroll
        for (int k = 1; k < 8; k++) {
            s.x += sh[k * 32 + c].x;
            s.y += sh[k * 32 + c].y;
        }
        atomicAdd(&g_pool[2 * c],     s.x);
        atomicAdd(&g_pool[2 * c + 1], s.y);
    }
}

// ---------------- head ------------------------------------------------------------
__global__ void k_head(const float* __restrict__ gf,
                       const float* __restrict__ w_glob, const float* __restrict__ b_glob,
                       const float* __restrict__ w_fc1, const float* __restrict__ b_fc1,
                       const float* __restrict__ w_fc2, const float* __restrict__ b_fc2,
                       float* __restrict__ out) {
    __shared__ float xc[2 * HDIM];
    __shared__ float t1[HDIM];
    int t = threadIdx.x;

    xc[t] = g_pool[t] * (1.0f / (float)N_NODES);

    float a = b_glob[t];
    #pragma unroll
    for (int k = 0; k < FGLOB; k++) a += gf[k] * w_glob[k * HDIM + t];
    xc[HDIM + t] = fmaxf(a, 0.f);
    __syncthreads();

    float u = b_fc1[t];
    #pragma unroll 8
    for (int k = 0; k < 2 * HDIM; k++) u += xc[k] * w_fc1[k * HDIM + t];
    t1[t] = fmaxf(u, 0.f);
    __syncthreads();

    float o = b_fc2[t];
    #pragma unroll 8
    for (int k = 0; k < HDIM; k++) o += t1[k] * w_fc2[k * OUTDIM + t];
    out[t] = o;
}

// ---------------- launch ------------------------------------------------------
extern "C" void kernel_launch(void* const* d_in, const int* in_sizes, int n_in,
                              void* d_out, int out_size) {
    const float* x      = (const float*)d_in[0];
    const int*   ei     = (const int*)  d_in[1];   // [2,E]: first E = src, next E = dst
    const float* gf     = (const float*)d_in[2];
    const float* w_node = (const float*)d_in[3];
    const float* b_node = (const float*)d_in[4];
    const float* w_glob = (const float*)d_in[5];
    const float* b_glob = (const float*)d_in[6];
    const float* w_c[3] = {(const float*)d_in[7], (const float*)d_in[9],  (const float*)d_in[11]};
    const float* b_c[3] = {(const float*)d_in[8], (const float*)d_in[10], (const float*)d_in[12]};
    const float* w_fc1  = (const float*)d_in[13];
    const float* b_fc1  = (const float*)d_in[14];
    const float* w_fc2  = (const float*)d_in[15];
    const float* b_fc2  = (const float*)d_in[16];
    float* out = (float*)d_out;

    __half *p_hf, *p_hwh;
    cudaGetSymbolAddress((void**)&p_hf,  g_hf);
    cudaGetSymbolAddress((void**)&p_hwh, g_hwh);

    static cudaStream_t s_side = nullptr;
    static cudaEvent_t  s_evFork = nullptr, s_evDis = nullptr, s_evFill = nullptr;
    if (!s_side) {
        cudaStreamCreateWithFlags(&s_side, cudaStreamNonBlocking);
        cudaEventCreateWithFlags(&s_evFork, cudaEventDisableTiming);
        cudaEventCreateWithFlags(&s_evDis,  cudaEventDisableTiming);
        cudaEventCreateWithFlags(&s_evFill, cudaEventDisableTiming);
    }

    const int TB = 256;

    // fork: CSR build chain on side stream
    cudaEventRecord(s_evFork, 0);
    cudaStreamWaitEvent(s_side, s_evFork, 0);
    k_init <<<(N_NODES + TB - 1) / TB, TB, 0, s_side>>>();
    k_count<<<(N_EDGES + TB - 1) / TB, TB, 0, s_side>>>(ei + N_EDGES);
    k_scan1<<<N_SCAN_BLOCKS, SCAN_BS, 0, s_side>>>();           // writes dis + cursor
    cudaEventRecord(s_evDis, s_side);
    k_scan2<<<1, 128, 0, s_side>>>();
    k_fill <<<(N_EDGES + TB - 1) / TB, TB, 0, s_side>>>(ei, ei + N_EDGES);
    cudaEventRecord(s_evFill, s_side);

    // main: embedding (no deps)
    k_embed<<<(N_NODES + 255) / 256, 256>>>(x, w_node, b_node, p_hf);

    const int HG = (N_NODES + 127) / 128;   // 782 blocks

    // layer 1 transform needs only dis
    cudaStreamWaitEvent(0, s_evDis, 0);
    k_hmma<<<HG, 256>>>(p_hf, w_c[0], p_hwh);
    // agg needs CSR
    cudaStreamWaitEvent(0, s_evFill, 0);
    k_agg<<<(N_NODES * 32 + TB - 1) / TB, TB>>>((const __half2*)p_hwh, b_c[0], (__half2*)p_hf);

    for (int l = 1; l < 3; l++) {
        k_hmma<<<HG, 256>>>(p_hf, w_c[l], p_hwh);
        k_agg<<<(N_NODES * 32 + TB - 1) / TB, TB>>>((const __half2*)p_hwh, b_c[l], (__half2*)p_hf);
    }

    // pool + head
    k_pool<<<256, 256>>>((const __half2*)p_hf);
    k_head<<<1, 64>>>(gf, w_glob, b_glob, w_fc1, b_fc1, w_fc2, b_fc2, out);
}

// round 7
// speedup vs baseline: 1.1765x; 1.1032x over previous
#include <cuda_runtime.h>
#include <cuda_fp16.h>
#include <cuda_fp8.h>
#include <cstdint>

#define N_NODES 100000
#define N_EDGES 1600000
#define FNODE   32
#define FGLOB   16
#define HDIM    64
#define OUTDIM  64

#define MSG_SCALE     64.0f
#define INV_MSG_SCALE (1.0f / 64.0f)

#define SCAN_BS 1024
#define N_SCAN_BLOCKS ((N_NODES + SCAN_BS - 1) / SCAN_BS)   // 98

// ---------------- scratch (device globals: no allocations allowed) ----------
__device__ int   g_cnt[N_NODES];
__device__ int   g_cursor[N_NODES];
__device__ int   g_rowoff[N_NODES];          // block-local exclusive scan
__device__ int   g_bsum[N_SCAN_BLOCKS];      // exclusive block offsets
__device__ __align__(16) int g_csr[N_EDGES];
__device__ float g_dis[N_NODES];
__device__ __align__(16) __half g_hf[(size_t)N_NODES * HDIM];        // node features fp16
__device__ __align__(16) unsigned int g_hw8[(size_t)N_NODES * 16];   // fp8x4 messages, 64B/row
__device__ float g_pool[HDIM];

// ---------------- init ---------------------------------------------------------
__global__ void k_init() {
    int i = blockIdx.x * blockDim.x + threadIdx.x;
    if (i < N_NODES) g_cnt[i] = 0;
    if (i < HDIM) g_pool[i] = 0.f;
}

// ---------------- degree count over dst ----------------------------------------
__global__ void k_count(const int* __restrict__ dst) {
    int e = blockIdx.x * blockDim.x + threadIdx.x;
    if (e < N_EDGES) atomicAdd(&g_cnt[dst[e]], 1);
}

// ---------------- scan stage 1 (shuffle-based) + dis + cursor zero --------------
__global__ void k_scan1() {
    __shared__ int wsum[32];
    int tid = threadIdx.x;
    int i = blockIdx.x * SCAN_BS + tid;
    int v = (i < N_NODES) ? g_cnt[i] : 0;
    if (i < N_NODES) {
        g_dis[i] = rsqrtf((float)(v + 1));
        g_cursor[i] = 0;
    }

    int lane = tid & 31, w = tid >> 5;
    int s = v;
    #pragma unroll
    for (int o = 1; o < 32; o <<= 1) {
        int t = __shfl_up_sync(0xffffffffu, s, o);
        if (lane >= o) s += t;
    }
    if (lane == 31) wsum[w] = s;
    __syncthreads();
    if (w == 0) {
        int ws = wsum[lane];
        int t = ws;
        #pragma unroll
        for (int o = 1; o < 32; o <<= 1) {
            int u = __shfl_up_sync(0xffffffffu, t, o);
            if (lane >= o) t += u;
        }
        wsum[lane] = t - ws;
        if (lane == 31) g_bsum[blockIdx.x] = t;
    }
    __syncthreads();
    if (i < N_NODES) g_rowoff[i] = wsum[w] + s - v;
}

// ---------------- scan stage 2 --------------------------------------------------
__global__ void k_scan2() {
    __shared__ int wsum[4];
    int tid = threadIdx.x;                 // 128 threads
    int v = (tid < N_SCAN_BLOCKS) ? g_bsum[tid] : 0;
    int lane = tid & 31, w = tid >> 5;
    int s = v;
    #pragma unroll
    for (int o = 1; o < 32; o <<= 1) {
        int t = __shfl_up_sync(0xffffffffu, s, o);
        if (lane >= o) s += t;
    }
    if (lane == 31) wsum[w] = s;
    __syncthreads();
    int woff = 0;
    #pragma unroll
    for (int k = 0; k < 4; k++) if (k < w) woff += wsum[k];
    if (tid < N_SCAN_BLOCKS) g_bsum[tid] = woff + s - v;
}

// ---------------- CSR fill ------------------------------------------------------
__global__ void k_fill(const int* __restrict__ src, const int* __restrict__ dst) {
    int e = blockIdx.x * blockDim.x + threadIdx.x;
    if (e < N_EDGES) {
        int d = dst[e];
        int base = g_rowoff[d] + g_bsum[d >> 10];
        int pos = base + atomicAdd(&g_cursor[d], 1);
        g_csr[pos] = src[e];
    }
}

// ---------------- embedding GEMM: hf[N,64] = fp16(x[N,32] @ W + b) --------------
__global__ void k_embed(const float* __restrict__ in, const float* __restrict__ w,
                        const float* __restrict__ bias, __half* __restrict__ out) {
    __shared__ float4 Ws4[FNODE * 16];
    __shared__ float Bs[HDIM];
    int tid = threadIdx.x;
    for (int j = tid; j < FNODE * 16; j += blockDim.x)
        Ws4[j] = reinterpret_cast<const float4*>(w)[j];
    if (tid < HDIM) Bs[tid] = bias[tid];
    __syncthreads();

    int colBase = (tid & 1) * 32;
    int cb4 = colBase >> 2;
    int pair = tid >> 1;
    int r0 = blockIdx.x * 256 + pair * 2;
    if (r0 >= N_NODES) return;
    bool v1 = (r0 + 1 < N_NODES);

    float acc0[32], acc1[32];
    #pragma unroll
    for (int c = 0; c < 32; c++) { acc0[c] = 0.f; acc1[c] = 0.f; }

    const float4* xr0 = reinterpret_cast<const float4*>(in + (size_t)r0 * FNODE);
    const float4* xr1 = reinterpret_cast<const float4*>(in + (size_t)(v1 ? r0 + 1 : r0) * FNODE);

    #pragma unroll
    for (int k4 = 0; k4 < FNODE / 4; ++k4) {
        float4 a = __ldg(&xr0[k4]);
        float4 b = __ldg(&xr1[k4]);
        const float av[4] = {a.x, a.y, a.z, a.w};
        const float bv[4] = {b.x, b.y, b.z, b.w};
        #pragma unroll
        for (int kk = 0; kk < 4; ++kk) {
            const float4* wrow = &Ws4[(k4 * 4 + kk) * 16 + cb4];
            float xa = av[kk], xb = bv[kk];
            #pragma unroll
            for (int c4 = 0; c4 < 8; c4++) {
                float4 wv = wrow[c4];
                acc0[c4*4+0] += xa * wv.x; acc1[c4*4+0] += xb * wv.x;
                acc0[c4*4+1] += xa * wv.y; acc1[c4*4+1] += xb * wv.y;
                acc0[c4*4+2] += xa * wv.z; acc1[c4*4+2] += xb * wv.z;
                acc0[c4*4+3] += xa * wv.w; acc1[c4*4+3] += xb * wv.w;
            }
        }
    }

    __half2 hb0[16], hb1[16];
    #pragma unroll
    for (int c2 = 0; c2 < 16; c2++) {
        hb0[c2] = __floats2half2_rn(acc0[2*c2] + Bs[colBase + 2*c2],
                                    acc0[2*c2+1] + Bs[colBase + 2*c2 + 1]);
        hb1[c2] = __floats2half2_rn(acc1[2*c2] + Bs[colBase + 2*c2],
                                    acc1[2*c2+1] + Bs[colBase + 2*c2 + 1]);
    }
    uint4* o0 = reinterpret_cast<uint4*>(out + (size_t)r0 * HDIM + colBase);
    const uint4* p0 = reinterpret_cast<const uint4*>(hb0);
    #pragma unroll
    for (int q = 0; q < 4; q++) o0[q] = p0[q];
    if (v1) {
        uint4* o1 = reinterpret_cast<uint4*>(out + (size_t)(r0 + 1) * HDIM + colBase);
        const uint4* p1 = reinterpret_cast<const uint4*>(hb1);
        #pragma unroll
        for (int q = 0; q < 4; q++) o1[q] = p1[q];
    }
}

// ---------------- HMMA conv transform: hw8 = fp8(64 * dis .* (hf @ W)) ----------
// Block: 256 threads = 8 warps, 128 rows. fp8 results staged via padded SMEM and
// copied out with coalesced uint2 stores.
#define APITCH 72      // halves; conflict-free ldmatrix
#define S8P    36      // ushorts per padded fp8 row (32 data + 4 pad)
__global__ void k_hmma(const __half* __restrict__ hin, const float* __restrict__ w,
                       unsigned int* __restrict__ out8) {
    __shared__ __half Wsm[HDIM * APITCH];
    __shared__ __half Asm[128 * APITCH];    // reused as fp8 staging after MMA
    int tid = threadIdx.x;
    int lane = tid & 31, wid = tid >> 5;
    int rowBase = blockIdx.x * 128;

    // stage W (fp32 -> fp16)
    for (int i = tid; i < HDIM * HDIM; i += 256) {
        int r = i >> 6, c = i & 63;
        Wsm[r * APITCH + c] = __float2half(w[i]);
    }
    // stage A rows (uint2 = 4 halves)
    for (int i = tid; i < 128 * 16; i += 256) {
        int r = i >> 4, c4 = i & 15;
        int gr = rowBase + r;
        uint2 v = make_uint2(0u, 0u);
        if (gr < N_NODES)
            v = *reinterpret_cast<const uint2*>(hin + (size_t)gr * HDIM + c4 * 4);
        *reinterpret_cast<uint2*>(&Asm[r * APITCH + c4 * 4]) = v;
    }
    __syncthreads();

    float acc[8][4];
    #pragma unroll
    for (int j = 0; j < 8; j++)
        #pragma unroll
        for (int q = 0; q < 4; q++) acc[j][q] = 0.f;

    uint32_t aAddr = (uint32_t)__cvta_generic_to_shared(
        &Asm[(wid * 16 + (lane & 15)) * APITCH + (lane >> 4) * 8]);
    uint32_t bAddr = (uint32_t)__cvta_generic_to_shared(
        &Wsm[(lane & 15) * APITCH]);

    #pragma unroll
    for (int k = 0; k < 4; k++) {
        uint32_t a0, a1, a2, a3;
        asm volatile("ldmatrix.sync.aligned.m8n8.x4.shared.b16 {%0,%1,%2,%3}, [%4];\n"
                     : "=r"(a0), "=r"(a1), "=r"(a2), "=r"(a3)
                     : "r"(aAddr + k * 16 * 2));
        #pragma unroll
        for (int j = 0; j < 8; j++) {
            uint32_t b0, b1;
            asm volatile("ldmatrix.sync.aligned.m8n8.x2.trans.shared.b16 {%0,%1}, [%2];\n"
                         : "=r"(b0), "=r"(b1)
                         : "r"(bAddr + (k * 16 * APITCH + j * 8) * 2));
            asm volatile("mma.sync.aligned.m16n8k16.row.col.f32.f16.f16.f32 "
                         "{%0,%1,%2,%3}, {%4,%5,%6,%7}, {%8,%9}, {%0,%1,%2,%3};\n"
                         : "+f"(acc[j][0]), "+f"(acc[j][1]), "+f"(acc[j][2]), "+f"(acc[j][3])
                         : "r"(a0), "r"(a1), "r"(a2), "r"(a3), "r"(b0), "r"(b1));
        }
    }

    // all ldmatrix reads of Asm are complete per-thread after the loop;
    // sync before reusing the buffer for fp8 staging
    __syncthreads();
    unsigned short* S8 = reinterpret_cast<unsigned short*>(Asm);   // [128][S8P]

    int g = lane >> 2, q = lane & 3;
    int r0l = wid * 16 + g;
    int r1l = r0l + 8;
    int gr0 = rowBase + r0l, gr1 = rowBase + r1l;
    float d0 = (gr0 < N_NODES) ? g_dis[gr0] * MSG_SCALE : 0.f;
    float d1 = (gr1 < N_NODES) ? g_dis[gr1] * MSG_SCALE : 0.f;
    #pragma unroll
    for (int j = 0; j < 8; j++) {
        S8[r0l * S8P + j * 4 + q] = __nv_cvt_float2_to_fp8x2(
            make_float2(acc[j][0] * d0, acc[j][1] * d0), __NV_SATFINITE, __NV_E4M3);
        S8[r1l * S8P + j * 4 + q] = __nv_cvt_float2_to_fp8x2(
            make_float2(acc[j][2] * d1, acc[j][3] * d1), __NV_SATFINITE, __NV_E4M3);
    }
    __syncthreads();

    // coalesced copy out: 128 rows x 8 uint2 (64B/row)
    for (int i = tid; i < 128 * 8; i += 256) {
        int r = i >> 3, c = i & 7;
        int grow = rowBase + r;
        if (grow < N_NODES) {
            uint2 v = *reinterpret_cast<const uint2*>(&S8[r * S8P + c * 4]);
            *reinterpret_cast<uint2*>(&out8[(size_t)grow * 16 + c * 2]) = v;
        }
    }
}

// ---------------- fp8x2 -> half2 helper -----------------------------------------
__device__ __forceinline__ __half2 fp8x2_to_h2(unsigned short u) {
    __half2_raw hr = __nv_cvt_fp8x2_to_halfraw2(u, __NV_E4M3);
    return *reinterpret_cast<__half2*>(&hr);
}

// ---------------- aggregation: warp/node, 16 lanes/row, 2 edges per LDG ---------
// hw8 rows (64B) pre-scaled by 64*dis[src]. hf[i] = fp16(relu(dis[i]/64*sum + b))
__global__ void k_agg(const unsigned int* __restrict__ hw,
                      const float* __restrict__ bias, __half* __restrict__ outh) {
    int gw = (blockIdx.x * blockDim.x + threadIdx.x) >> 5;
    int lane = threadIdx.x & 31;
    if (gw >= N_NODES) return;
    int hf = lane >> 4;          // 0: even edges, 1: odd edges
    int sub = lane & 15;         // uint column (4 fp8 cols)

    __half2 a0 = __float2half2_rn(0.f);
    __half2 a1 = a0;

    // self loop (half 0 only; hw8 already includes 64*dis[i])
    if (hf == 0) {
        unsigned int v = __ldg(&hw[(size_t)gw * 16 + sub]);
        a0 = fp8x2_to_h2((unsigned short)(v & 0xffffu));
        a1 = fp8x2_to_h2((unsigned short)(v >> 16));
    }

    int beg = g_rowoff[gw] + g_bsum[gw >> 10];
    int end = beg + g_cnt[gw];
    int j = beg;

    if (j < end && (j & 1)) {    // align to even index; half0 takes the odd start
        if (hf == 0) {
            int idx = __ldg(&g_csr[j]);
            unsigned int v = __ldg(&hw[(size_t)idx * 16 + sub]);
            a0 = __hadd2(a0, fp8x2_to_h2((unsigned short)(v & 0xffffu)));
            a1 = __hadd2(a1, fp8x2_to_h2((unsigned short)(v >> 16)));
        }
        ++j;
    }
    const int2* csr2 = reinterpret_cast<const int2*>(g_csr);
    for (; j + 1 < end; j += 2) {
        int2 e = __ldg(&csr2[j >> 1]);
        int idx = hf ? e.y : e.x;
        unsigned int v = __ldg(&hw[(size_t)idx * 16 + sub]);
        a0 = __hadd2(a0, fp8x2_to_h2((unsigned short)(v & 0xffffu)));
        a1 = __hadd2(a1, fp8x2_to_h2((unsigned short)(v >> 16)));
    }
    if (j < end && hf == 0) {    // tail edge
        int idx = __ldg(&g_csr[j]);
        unsigned int v = __ldg(&hw[(size_t)idx * 16 + sub]);
        a0 = __hadd2(a0, fp8x2_to_h2((unsigned short)(v & 0xffffu)));
        a1 = __hadd2(a1, fp8x2_to_h2((unsigned short)(v >> 16)));
    }

    // combine the two half-warps (lanes 0-15 <- +lanes 16-31)
    float2 f0 = __half22float2(a0);
    float2 f1 = __half22float2(a1);
    f0.x += __shfl_down_sync(0xffffffffu, f0.x, 16);
    f0.y += __shfl_down_sync(0xffffffffu, f0.y, 16);
    f1.x += __shfl_down_sync(0xffffffffu, f1.x, 16);
    f1.y += __shfl_down_sync(0xffffffffu, f1.y, 16);

    if (hf == 0) {
        float di = g_dis[gw] * INV_MSG_SCALE;
        float4 b4 = __ldg(reinterpret_cast<const float4*>(bias) + sub);
        __half2 o0 = __floats2half2_rn(fmaxf(fmaf(di, f0.x, b4.x), 0.f),
                                       fmaxf(fmaf(di, f0.y, b4.y), 0.f));
        __half2 o1 = __floats2half2_rn(fmaxf(fmaf(di, f1.x, b4.z), 0.f),
                                       fmaxf(fmaf(di, f1.y, b4.w), 0.f));
        uint2 st;
        st.x = *reinterpret_cast<unsigned int*>(&o0);
        st.y = *reinterpret_cast<unsigned int*>(&o1);
        *reinterpret_cast<uint2*>(outh + (size_t)gw * HDIM + sub * 4) = st;
    }
}

// ---------------- mean pool over nodes (fp16 input) ------------------------------
__global__ void k_pool(const __half2* __restrict__ h2) {
    __shared__ float2 sh[256];
    int c = threadIdx.x & 31;       // half2 column
    int seg = threadIdx.x >> 5;     // 0..7
    float2 acc = make_float2(0.f, 0.f);
    for (int r = blockIdx.x * 8 + seg; r < N_NODES; r += gridDim.x * 8) {
        float2 v = __half22float2(h2[(size_t)r * 32 + c]);
        acc.x += v.x; acc.y += v.y;
    }
    sh[threadIdx.x] = acc;
    __syncthreads();
    if (threadIdx.x < 32) {
        float2 s = sh[c];
        #pragma unroll
        for (int k = 1; k < 8; k++) {
            s.x += sh[k * 32 + c].x;
            s.y += sh[k * 32 + c].y;
        }
        atomicAdd(&g_pool[2 * c],     s.x);
        atomicAdd(&g_pool[2 * c + 1], s.y);
    }
}

// ---------------- head ------------------------------------------------------------
__global__ void k_head(const float* __restrict__ gf,
                       const float* __restrict__ w_glob, const float* __restrict__ b_glob,
                       const float* __restrict__ w_fc1, const float* __restrict__ b_fc1,
                       const float* __restrict__ w_fc2, const float* __restrict__ b_fc2,
                       float* __restrict__ out) {
    __shared__ float xc[2 * HDIM];
    __shared__ float t1[HDIM];
    int t = threadIdx.x;

    xc[t] = g_pool[t] * (1.0f / (float)N_NODES);

    float a = b_glob[t];
    #pragma unroll
    for (int k = 0; k < FGLOB; k++) a += gf[k] * w_glob[k * HDIM + t];
    xc[HDIM + t] = fmaxf(a, 0.f);
    __syncthreads();

    float u = b_fc1[t];
    #pragma unroll 8
    for (int k = 0; k < 2 * HDIM; k++) u += xc[k] * w_fc1[k * HDIM + t];
    t1[t] = fmaxf(u, 0.f);
    __syncthreads();

    float o = b_fc2[t];
    #pragma unroll 8
    for (int k = 0; k < HDIM; k++) o += t1[k] * w_fc2[k * OUTDIM + t];
    out[t] = o;
}

// ---------------- launch ------------------------------------------------------
extern "C" void kernel_launch(void* const* d_in, const int* in_sizes, int n_in,
                              void* d_out, int out_size) {
    const float* x      = (const float*)d_in[0];
    const int*   ei     = (const int*)  d_in[1];   // [2,E]: first E = src, next E = dst
    const float* gf     = (const float*)d_in[2];
    const float* w_node = (const float*)d_in[3];
    const float* b_node = (const float*)d_in[4];
    const float* w_glob = (const float*)d_in[5];
    const float* b_glob = (const float*)d_in[6];
    const float* w_c[3] = {(const float*)d_in[7], (const float*)d_in[9],  (const float*)d_in[11]};
    const float* b_c[3] = {(const float*)d_in[8], (const float*)d_in[10], (const float*)d_in[12]};
    const float* w_fc1  = (const float*)d_in[13];
    const float* b_fc1  = (const float*)d_in[14];
    const float* w_fc2  = (const float*)d_in[15];
    const float* b_fc2  = (const float*)d_in[16];
    float* out = (float*)d_out;

    __half *p_hf;
    unsigned int *p_hw8;
    cudaGetSymbolAddress((void**)&p_hf,  g_hf);
    cudaGetSymbolAddress((void**)&p_hw8, g_hw8);

    static cudaStream_t s_side = nullptr;
    static cudaEvent_t  s_evFork = nullptr, s_evDis = nullptr, s_evFill = nullptr;
    if (!s_side) {
        cudaStreamCreateWithFlags(&s_side, cudaStreamNonBlocking);
        cudaEventCreateWithFlags(&s_evFork, cudaEventDisableTiming);
        cudaEventCreateWithFlags(&s_evDis,  cudaEventDisableTiming);
        cudaEventCreateWithFlags(&s_evFill, cudaEventDisableTiming);
    }

    const int TB = 256;

    // fork: CSR build chain on side stream
    cudaEventRecord(s_evFork, 0);
    cudaStreamWaitEvent(s_side, s_evFork, 0);
    k_init <<<(N_NODES + TB - 1) / TB, TB, 0, s_side>>>();
    k_count<<<(N_EDGES + TB - 1) / TB, TB, 0, s_side>>>(ei + N_EDGES);
    k_scan1<<<N_SCAN_BLOCKS, SCAN_BS, 0, s_side>>>();           // writes dis + cursor
    cudaEventRecord(s_evDis, s_side);
    k_scan2<<<1, 128, 0, s_side>>>();
    k_fill <<<(N_EDGES + TB - 1) / TB, TB, 0, s_side>>>(ei, ei + N_EDGES);
    cudaEventRecord(s_evFill, s_side);

    // main: embedding (no deps)
    k_embed<<<(N_NODES + 255) / 256, 256>>>(x, w_node, b_node, p_hf);

    const int HG = (N_NODES + 127) / 128;   // 782 blocks

    // layer 1 transform needs only dis
    cudaStreamWaitEvent(0, s_evDis, 0);
    k_hmma<<<HG, 256>>>(p_hf, w_c[0], p_hw8);
    // agg needs CSR
    cudaStreamWaitEvent(0, s_evFill, 0);
    k_agg<<<(N_NODES * 32 + TB - 1) / TB, TB>>>(p_hw8, b_c[0], p_hf);

    for (int l = 1; l < 3; l++) {
        k_hmma<<<HG, 256>>>(p_hf, w_c[l], p_hw8);
        k_agg<<<(N_NODES * 32 + TB - 1) / TB, TB>>>(p_hw8, b_c[l], p_hf);
    }

    // pool + head
    k_pool<<<256, 256>>>((const __half2*)p_hf);
    k_head<<<1, 64>>>(gf, w_glob, b_glob, w_fc1, b_fc1, w_fc2, b_fc2, out);
}

// round 8
// speedup vs baseline: 1.2944x; 1.1003x over previous
#include <cuda_runtime.h>
#include <cuda_fp16.h>
#include <cuda_fp8.h>
#include <cstdint>

#define N_NODES 100000
#define N_EDGES 1600000
#define FNODE   32
#define FGLOB   16
#define HDIM    64
#define OUTDIM  64

#define MSG_SCALE     64.0f
#define INV_MSG_SCALE (1.0f / 64.0f)

#define SCAN_BS 1024
#define N_SCAN_BLOCKS ((N_NODES + SCAN_BS - 1) / SCAN_BS)   // 98

// ---------------- scratch (device globals: no allocations allowed) ----------
__device__ int   g_cnt[N_NODES];
__device__ int   g_cursor[N_NODES];
__device__ int   g_rowoff[N_NODES];          // block-local exclusive scan
__device__ int   g_bsum[N_SCAN_BLOCKS];      // exclusive block offsets
__device__ __align__(16) int g_csr[N_EDGES];
__device__ float g_dis[N_NODES];
__device__ __align__(16) __half g_hf[(size_t)N_NODES * HDIM];        // node features fp16
__device__ __align__(16) unsigned int g_hw8[(size_t)N_NODES * 16];   // fp8x4 messages, 64B/row
__device__ float g_pool[HDIM];

// ---------------- init ---------------------------------------------------------
__global__ void k_init() {
    int i = blockIdx.x * blockDim.x + threadIdx.x;
    if (i < N_NODES) g_cnt[i] = 0;
    if (i < HDIM) g_pool[i] = 0.f;
}

// ---------------- degree count over dst ----------------------------------------
__global__ void k_count(const int* __restrict__ dst) {
    int e = blockIdx.x * blockDim.x + threadIdx.x;
    if (e < N_EDGES) atomicAdd(&g_cnt[dst[e]], 1);
}

// ---------------- scan stage 1 (shuffle-based) + dis + cursor zero --------------
__global__ void k_scan1() {
    __shared__ int wsum[32];
    int tid = threadIdx.x;
    int i = blockIdx.x * SCAN_BS + tid;
    int v = (i < N_NODES) ? g_cnt[i] : 0;
    if (i < N_NODES) {
        g_dis[i] = rsqrtf((float)(v + 1));
        g_cursor[i] = 0;
    }

    int lane = tid & 31, w = tid >> 5;
    int s = v;
    #pragma unroll
    for (int o = 1; o < 32; o <<= 1) {
        int t = __shfl_up_sync(0xffffffffu, s, o);
        if (lane >= o) s += t;
    }
    if (lane == 31) wsum[w] = s;
    __syncthreads();
    if (w == 0) {
        int ws = wsum[lane];
        int t = ws;
        #pragma unroll
        for (int o = 1; o < 32; o <<= 1) {
            int u = __shfl_up_sync(0xffffffffu, t, o);
            if (lane >= o) t += u;
        }
        wsum[lane] = t - ws;
        if (lane == 31) g_bsum[blockIdx.x] = t;
    }
    __syncthreads();
    if (i < N_NODES) g_rowoff[i] = wsum[w] + s - v;
}

// ---------------- scan stage 2 --------------------------------------------------
__global__ void k_scan2() {
    __shared__ int wsum[4];
    int tid = threadIdx.x;                 // 128 threads
    int v = (tid < N_SCAN_BLOCKS) ? g_bsum[tid] : 0;
    int lane = tid & 31, w = tid >> 5;
    int s = v;
    #pragma unroll
    for (int o = 1; o < 32; o <<= 1) {
        int t = __shfl_up_sync(0xffffffffu, s, o);
        if (lane >= o) s += t;
    }
    if (lane == 31) wsum[w] = s;
    __syncthreads();
    int woff = 0;
    #pragma unroll
    for (int k = 0; k < 4; k++) if (k < w) woff += wsum[k];
    if (tid < N_SCAN_BLOCKS) g_bsum[tid] = woff + s - v;
}

// ---------------- CSR fill ------------------------------------------------------
__global__ void k_fill(const int* __restrict__ src, const int* __restrict__ dst) {
    int e = blockIdx.x * blockDim.x + threadIdx.x;
    if (e < N_EDGES) {
        int d = dst[e];
        int base = g_rowoff[d] + g_bsum[d >> 10];
        int pos = base + atomicAdd(&g_cursor[d], 1);
        g_csr[pos] = src[e];
    }
}

// ---------------- embedding GEMM: hf[N,64] = fp16(x[N,32] @ W + b) --------------
__global__ void k_embed(const float* __restrict__ in, const float* __restrict__ w,
                        const float* __restrict__ bias, __half* __restrict__ out) {
    __shared__ float4 Ws4[FNODE * 16];
    __shared__ float Bs[HDIM];
    int tid = threadIdx.x;
    for (int j = tid; j < FNODE * 16; j += blockDim.x)
        Ws4[j] = reinterpret_cast<const float4*>(w)[j];
    if (tid < HDIM) Bs[tid] = bias[tid];
    __syncthreads();

    int colBase = (tid & 1) * 32;
    int cb4 = colBase >> 2;
    int pair = tid >> 1;
    int r0 = blockIdx.x * 256 + pair * 2;
    if (r0 >= N_NODES) return;
    bool v1 = (r0 + 1 < N_NODES);

    float acc0[32], acc1[32];
    #pragma unroll
    for (int c = 0; c < 32; c++) { acc0[c] = 0.f; acc1[c] = 0.f; }

    const float4* xr0 = reinterpret_cast<const float4*>(in + (size_t)r0 * FNODE);
    const float4* xr1 = reinterpret_cast<const float4*>(in + (size_t)(v1 ? r0 + 1 : r0) * FNODE);

    #pragma unroll
    for (int k4 = 0; k4 < FNODE / 4; ++k4) {
        float4 a = __ldg(&xr0[k4]);
        float4 b = __ldg(&xr1[k4]);
        const float av[4] = {a.x, a.y, a.z, a.w};
        const float bv[4] = {b.x, b.y, b.z, b.w};
        #pragma unroll
        for (int kk = 0; kk < 4; ++kk) {
            const float4* wrow = &Ws4[(k4 * 4 + kk) * 16 + cb4];
            float xa = av[kk], xb = bv[kk];
            #pragma unroll
            for (int c4 = 0; c4 < 8; c4++) {
                float4 wv = wrow[c4];
                acc0[c4*4+0] += xa * wv.x; acc1[c4*4+0] += xb * wv.x;
                acc0[c4*4+1] += xa * wv.y; acc1[c4*4+1] += xb * wv.y;
                acc0[c4*4+2] += xa * wv.z; acc1[c4*4+2] += xb * wv.z;
                acc0[c4*4+3] += xa * wv.w; acc1[c4*4+3] += xb * wv.w;
            }
        }
    }

    __half2 hb0[16], hb1[16];
    #pragma unroll
    for (int c2 = 0; c2 < 16; c2++) {
        hb0[c2] = __floats2half2_rn(acc0[2*c2] + Bs[colBase + 2*c2],
                                    acc0[2*c2+1] + Bs[colBase + 2*c2 + 1]);
        hb1[c2] = __floats2half2_rn(acc1[2*c2] + Bs[colBase + 2*c2],
                                    acc1[2*c2+1] + Bs[colBase + 2*c2 + 1]);
    }
    uint4* o0 = reinterpret_cast<uint4*>(out + (size_t)r0 * HDIM + colBase);
    const uint4* p0 = reinterpret_cast<const uint4*>(hb0);
    #pragma unroll
    for (int q = 0; q < 4; q++) o0[q] = p0[q];
    if (v1) {
        uint4* o1 = reinterpret_cast<uint4*>(out + (size_t)(r0 + 1) * HDIM + colBase);
        const uint4* p1 = reinterpret_cast<const uint4*>(hb1);
        #pragma unroll
        for (int q = 0; q < 4; q++) o1[q] = p1[q];
    }
}

// ---------------- HMMA conv transform: hw8 = fp8(64 * dis .* (hf @ W)) ----------
// Block: 256 threads = 8 warps, 128 rows. fp8 results staged via padded SMEM and
// copied out with coalesced uint2 stores.
#define APITCH 72      // halves; conflict-free ldmatrix
#define S8P    36      // ushorts per padded fp8 row (32 data + 4 pad)
__global__ void k_hmma(const __half* __restrict__ hin, const float* __restrict__ w,
                       unsigned int* __restrict__ out8) {
    __shared__ __half Wsm[HDIM * APITCH];
    __shared__ __half Asm[128 * APITCH];    // reused as fp8 staging after MMA
    int tid = threadIdx.x;
    int lane = tid & 31, wid = tid >> 5;
    int rowBase = blockIdx.x * 128;

    // stage W (fp32 -> fp16)
    for (int i = tid; i < HDIM * HDIM; i += 256) {
        int r = i >> 6, c = i & 63;
        Wsm[r * APITCH + c] = __float2half(w[i]);
    }
    // stage A rows (uint2 = 4 halves)
    for (int i = tid; i < 128 * 16; i += 256) {
        int r = i >> 4, c4 = i & 15;
        int gr = rowBase + r;
        uint2 v = make_uint2(0u, 0u);
        if (gr < N_NODES)
            v = *reinterpret_cast<const uint2*>(hin + (size_t)gr * HDIM + c4 * 4);
        *reinterpret_cast<uint2*>(&Asm[r * APITCH + c4 * 4]) = v;
    }
    __syncthreads();

    float acc[8][4];
    #pragma unroll
    for (int j = 0; j < 8; j++)
        #pragma unroll
        for (int q = 0; q < 4; q++) acc[j][q] = 0.f;

    uint32_t aAddr = (uint32_t)__cvta_generic_to_shared(
        &Asm[(wid * 16 + (lane & 15)) * APITCH + (lane >> 4) * 8]);
    uint32_t bAddr = (uint32_t)__cvta_generic_to_shared(
        &Wsm[(lane & 15) * APITCH]);

    #pragma unroll
    for (int k = 0; k < 4; k++) {
        uint32_t a0, a1, a2, a3;
        asm volatile("ldmatrix.sync.aligned.m8n8.x4.shared.b16 {%0,%1,%2,%3}, [%4];\n"
                     : "=r"(a0), "=r"(a1), "=r"(a2), "=r"(a3)
                     : "r"(aAddr + k * 16 * 2));
        #pragma unroll
        for (int j = 0; j < 8; j++) {
            uint32_t b0, b1;
            asm volatile("ldmatrix.sync.aligned.m8n8.x2.trans.shared.b16 {%0,%1}, [%2];\n"
                         : "=r"(b0), "=r"(b1)
                         : "r"(bAddr + (k * 16 * APITCH + j * 8) * 2));
            asm volatile("mma.sync.aligned.m16n8k16.row.col.f32.f16.f16.f32 "
                         "{%0,%1,%2,%3}, {%4,%5,%6,%7}, {%8,%9}, {%0,%1,%2,%3};\n"
                         : "+f"(acc[j][0]), "+f"(acc[j][1]), "+f"(acc[j][2]), "+f"(acc[j][3])
                         : "r"(a0), "r"(a1), "r"(a2), "r"(a3), "r"(b0), "r"(b1));
        }
    }

    __syncthreads();
    unsigned short* S8 = reinterpret_cast<unsigned short*>(Asm);   // [128][S8P]

    int g = lane >> 2, q = lane & 3;
    int r0l = wid * 16 + g;
    int r1l = r0l + 8;
    int gr0 = rowBase + r0l, gr1 = rowBase + r1l;
    float d0 = (gr0 < N_NODES) ? g_dis[gr0] * MSG_SCALE : 0.f;
    float d1 = (gr1 < N_NODES) ? g_dis[gr1] * MSG_SCALE : 0.f;
    #pragma unroll
    for (int j = 0; j < 8; j++) {
        S8[r0l * S8P + j * 4 + q] = __nv_cvt_float2_to_fp8x2(
            make_float2(acc[j][0] * d0, acc[j][1] * d0), __NV_SATFINITE, __NV_E4M3);
        S8[r1l * S8P + j * 4 + q] = __nv_cvt_float2_to_fp8x2(
            make_float2(acc[j][2] * d1, acc[j][3] * d1), __NV_SATFINITE, __NV_E4M3);
    }
    __syncthreads();

    // coalesced copy out: 128 rows x 8 uint2 (64B/row)
    for (int i = tid; i < 128 * 8; i += 256) {
        int r = i >> 3, c = i & 7;
        int grow = rowBase + r;
        if (grow < N_NODES) {
            uint2 v = *reinterpret_cast<const uint2*>(&S8[r * S8P + c * 4]);
            *reinterpret_cast<uint2*>(&out8[(size_t)grow * 16 + c * 2]) = v;
        }
    }
}

// ---------------- fp8x2 -> half2 helper -----------------------------------------
__device__ __forceinline__ __half2 fp8x2_to_h2(unsigned short u) {
    __half2_raw hr = __nv_cvt_fp8x2_to_halfraw2(u, __NV_E4M3);
    return *reinterpret_cast<__half2*>(&hr);
}
__device__ __forceinline__ __half2 u2h2(unsigned int u) {
    return *reinterpret_cast<__half2*>(&u);
}

// ---------------- aggregation: warp/node, 8 lanes/row, 4 edges per LDG ----------
// hw8 rows (64B) pre-scaled by 64*dis[src]. hf[i] = fp16(relu(dis[i]/64*sum + b))
__global__ void k_agg(const uint2* __restrict__ hw,
                      const float* __restrict__ bias, __half* __restrict__ outh) {
    int gw = (blockIdx.x * blockDim.x + threadIdx.x) >> 5;
    int lane = threadIdx.x & 31;
    if (gw >= N_NODES) return;
    int e = lane >> 3;           // edge slot 0..3
    int s = lane & 7;            // uint2 column (8 fp8 cols)

    __half2 acc0 = __float2half2_rn(0.f), acc1 = acc0, acc2 = acc0, acc3 = acc0;

    // self loop on slot 0 (hw8 already includes 64*dis[i])
    if (e == 0) {
        uint2 v = __ldg(&hw[(size_t)gw * 8 + s]);
        acc0 = fp8x2_to_h2((unsigned short)(v.x & 0xffffu));
        acc1 = fp8x2_to_h2((unsigned short)(v.x >> 16));
        acc2 = fp8x2_to_h2((unsigned short)(v.y & 0xffffu));
        acc3 = fp8x2_to_h2((unsigned short)(v.y >> 16));
    }

    int beg = g_rowoff[gw] + g_bsum[gw >> 10];
    int end = beg + g_cnt[gw];
    int j = beg;
    for (; j + 4 <= end; j += 4) {
        int idx = __ldg(&g_csr[j + e]);
        uint2 v = __ldg(&hw[(size_t)idx * 8 + s]);
        acc0 = __hadd2(acc0, fp8x2_to_h2((unsigned short)(v.x & 0xffffu)));
        acc1 = __hadd2(acc1, fp8x2_to_h2((unsigned short)(v.x >> 16)));
        acc2 = __hadd2(acc2, fp8x2_to_h2((unsigned short)(v.y & 0xffffu)));
        acc3 = __hadd2(acc3, fp8x2_to_h2((unsigned short)(v.y >> 16)));
    }
    int rem = end - j;           // 0..3, warp-uniform
    if (e < rem) {
        int idx = __ldg(&g_csr[j + e]);
        uint2 v = __ldg(&hw[(size_t)idx * 8 + s]);
        acc0 = __hadd2(acc0, fp8x2_to_h2((unsigned short)(v.x & 0xffffu)));
        acc1 = __hadd2(acc1, fp8x2_to_h2((unsigned short)(v.x >> 16)));
        acc2 = __hadd2(acc2, fp8x2_to_h2((unsigned short)(v.y & 0xffffu)));
        acc3 = __hadd2(acc3, fp8x2_to_h2((unsigned short)(v.y >> 16)));
    }

    // reduce across edge slots (xor 8, then 16); all lanes participate
    unsigned ua0 = *reinterpret_cast<unsigned*>(&acc0);
    unsigned ua1 = *reinterpret_cast<unsigned*>(&acc1);
    unsigned ua2 = *reinterpret_cast<unsigned*>(&acc2);
    unsigned ua3 = *reinterpret_cast<unsigned*>(&acc3);
    acc0 = __hadd2(u2h2(ua0), u2h2(__shfl_xor_sync(0xffffffffu, ua0, 8)));
    acc1 = __hadd2(u2h2(ua1), u2h2(__shfl_xor_sync(0xffffffffu, ua1, 8)));
    acc2 = __hadd2(u2h2(ua2), u2h2(__shfl_xor_sync(0xffffffffu, ua2, 8)));
    acc3 = __hadd2(u2h2(ua3), u2h2(__shfl_xor_sync(0xffffffffu, ua3, 8)));
    ua0 = *reinterpret_cast<unsigned*>(&acc0);
    ua1 = *reinterpret_cast<unsigned*>(&acc1);
    ua2 = *reinterpret_cast<unsigned*>(&acc2);
    ua3 = *reinterpret_cast<unsigned*>(&acc3);
    acc0 = __hadd2(u2h2(ua0), u2h2(__shfl_xor_sync(0xffffffffu, ua0, 16)));
    acc1 = __hadd2(u2h2(ua1), u2h2(__shfl_xor_sync(0xffffffffu, ua1, 16)));
    acc2 = __hadd2(u2h2(ua2), u2h2(__shfl_xor_sync(0xffffffffu, ua2, 16)));
    acc3 = __hadd2(u2h2(ua3), u2h2(__shfl_xor_sync(0xffffffffu, ua3, 16)));

    if (e == 0) {
        float di = g_dis[gw] * INV_MSG_SCALE;
        float4 bA = __ldg(reinterpret_cast<const float4*>(bias) + 2 * s);
        float4 bB = __ldg(reinterpret_cast<const float4*>(bias) + 2 * s + 1);
        float2 f0 = __half22float2(acc0), f1 = __half22float2(acc1);
        float2 f2 = __half22float2(acc2), f3 = __half22float2(acc3);
        __half2 o0 = __floats2half2_rn(fmaxf(fmaf(di, f0.x, bA.x), 0.f),
                                       fmaxf(fmaf(di, f0.y, bA.y), 0.f));
        __half2 o1 = __floats2half2_rn(fmaxf(fmaf(di, f1.x, bA.z), 0.f),
                                       fmaxf(fmaf(di, f1.y, bA.w), 0.f));
        __half2 o2 = __floats2half2_rn(fmaxf(fmaf(di, f2.x, bB.x), 0.f),
                                       fmaxf(fmaf(di, f2.y, bB.y), 0.f));
        __half2 o3 = __floats2half2_rn(fmaxf(fmaf(di, f3.x, bB.z), 0.f),
                                       fmaxf(fmaf(di, f3.y, bB.w), 0.f));
        uint4 st;
        st.x = *reinterpret_cast<unsigned*>(&o0);
        st.y = *reinterpret_cast<unsigned*>(&o1);
        st.z = *reinterpret_cast<unsigned*>(&o2);
        st.w = *reinterpret_cast<unsigned*>(&o3);
        *reinterpret_cast<uint4*>(outh + (size_t)gw * HDIM + s * 8) = st;
    }
}

// ---------------- mean pool over nodes (fp16 input) ------------------------------
__global__ void k_pool(const __half2* __restrict__ h2) {
    __shared__ float2 sh[256];
    int c = threadIdx.x & 31;       // half2 column
    int seg = threadIdx.x >> 5;     // 0..7
    float2 acc = make_float2(0.f, 0.f);
    for (int r = blockIdx.x * 8 + seg; r < N_NODES; r += gridDim.x * 8) {
        float2 v = __half22float2(h2[(size_t)r * 32 + c]);
        acc.x += v.x; acc.y += v.y;
    }
    sh[threadIdx.x] = acc;
    __syncthreads();
    if (threadIdx.x < 32) {
        float2 s = sh[c];
        #pragma unroll
        for (int k = 1; k < 8; k++) {
            s.x += sh[k * 32 + c].x;
            s.y += sh[k * 32 + c].y;
        }
        atomicAdd(&g_pool[2 * c],     s.x);
        atomicAdd(&g_pool[2 * c + 1], s.y);
    }
}

// ---------------- head ------------------------------------------------------------
__global__ void k_head(const float* __restrict__ gf,
                       const float* __restrict__ w_glob, const float* __restrict__ b_glob,
                       const float* __restrict__ w_fc1, const float* __restrict__ b_fc1,
                       const float* __restrict__ w_fc2, const float* __restrict__ b_fc2,
                       float* __restrict__ out) {
    __shared__ float xc[2 * HDIM];
    __shared__ float t1[HDIM];
    int t = threadIdx.x;

    xc[t] = g_pool[t] * (1.0f / (float)N_NODES);

    float a = b_glob[t];
    #pragma unroll
    for (int k = 0; k < FGLOB; k++) a += gf[k] * w_glob[k * HDIM + t];
    xc[HDIM + t] = fmaxf(a, 0.f);
    __syncthreads();

    float u = b_fc1[t];
    #pragma unroll 8
    for (int k = 0; k < 2 * HDIM; k++) u += xc[k] * w_fc1[k * HDIM + t];
    t1[t] = fmaxf(u, 0.f);
    __syncthreads();

    float o = b_fc2[t];
    #pragma unroll 8
    for (int k = 0; k < HDIM; k++) o += t1[k] * w_fc2[k * OUTDIM + t];
    out[t] = o;
}

// ---------------- launch ------------------------------------------------------
extern "C" void kernel_launch(void* const* d_in, const int* in_sizes, int n_in,
                              void* d_out, int out_size) {
    const float* x      = (const float*)d_in[0];
    const int*   ei     = (const int*)  d_in[1];   // [2,E]: first E = src, next E = dst
    const float* gf     = (const float*)d_in[2];
    const float* w_node = (const float*)d_in[3];
    const float* b_node = (const float*)d_in[4];
    const float* w_glob = (const float*)d_in[5];
    const float* b_glob = (const float*)d_in[6];
    const float* w_c[3] = {(const float*)d_in[7], (const float*)d_in[9],  (const float*)d_in[11]};
    const float* b_c[3] = {(const float*)d_in[8], (const float*)d_in[10], (const float*)d_in[12]};
    const float* w_fc1  = (const float*)d_in[13];
    const float* b_fc1  = (const float*)d_in[14];
    const float* w_fc2  = (const float*)d_in[15];
    const float* b_fc2  = (const float*)d_in[16];
    float* out = (float*)d_out;

    __half *p_hf;
    unsigned int *p_hw8;
    cudaGetSymbolAddress((void**)&p_hf,  g_hf);
    cudaGetSymbolAddress((void**)&p_hw8, g_hw8);

    static cudaStream_t s_side = nullptr;
    static cudaEvent_t  s_evFork = nullptr, s_evDis = nullptr, s_evFill = nullptr;
    if (!s_side) {
        cudaStreamCreateWithFlags(&s_side, cudaStreamNonBlocking);
        cudaEventCreateWithFlags(&s_evFork, cudaEventDisableTiming);
        cudaEventCreateWithFlags(&s_evDis,  cudaEventDisableTiming);
        cudaEventCreateWithFlags(&s_evFill, cudaEventDisableTiming);
    }

    const int TB = 256;

    // fork: CSR build chain on side stream
    cudaEventRecord(s_evFork, 0);
    cudaStreamWaitEvent(s_side, s_evFork, 0);
    k_init <<<(N_NODES + TB - 1) / TB, TB, 0, s_side>>>();
    k_count<<<(N_EDGES + TB - 1) / TB, TB, 0, s_side>>>(ei + N_EDGES);
    k_scan1<<<N_SCAN_BLOCKS, SCAN_BS, 0, s_side>>>();           // writes dis + cursor
    cudaEventRecord(s_evDis, s_side);
    k_scan2<<<1, 128, 0, s_side>>>();
    k_fill <<<(N_EDGES + TB - 1) / TB, TB, 0, s_side>>>(ei, ei + N_EDGES);
    cudaEventRecord(s_evFill, s_side);

    // main: embedding (no deps)
    k_embed<<<(N_NODES + 255) / 256, 256>>>(x, w_node, b_node, p_hf);

    const int HG = (N_NODES + 127) / 128;   // 782 blocks

    // layer 1 transform needs only dis
    cudaStreamWaitEvent(0, s_evDis, 0);
    k_hmma<<<HG, 256>>>(p_hf, w_c[0], p_hw8);
    // agg needs CSR
    cudaStreamWaitEvent(0, s_evFill, 0);
    k_agg<<<(N_NODES * 32 + TB - 1) / TB, TB>>>((const uint2*)p_hw8, b_c[0], p_hf);

    for (int l = 1; l < 3; l++) {
        k_hmma<<<HG, 256>>>(p_hf, w_c[l], p_hw8);
        k_agg<<<(N_NODES * 32 + TB - 1) / TB, TB>>>((const uint2*)p_hw8, b_c[l], p_hf);
    }

    // pool + head
    k_pool<<<256, 256>>>((const __half2*)p_hf);
    k_head<<<1, 64>>>(gf, w_glob, b_glob, w_fc1, b_fc1, w_fc2, b_fc2, out);
}